// round 2
// baseline (speedup 1.0000x reference)
#include <cuda_runtime.h>

#define NN 40000
#define EE 640000
#define HD 128
#define GG 64

// ---------------- scratch (no allocs allowed: __device__ globals) ----------
__device__ __align__(16) float g_xw [(size_t)NN * HD];   // x@W (both layers)
__device__ __align__(16) float g_agg[(size_t)NN * HD];   // edge aggregation
__device__ __align__(16) float g_h  [(size_t)NN * HD];   // layer output
__device__ __align__(16) float g_deg [NN];
__device__ __align__(16) float g_dinv[NN];
__device__ __align__(16) float g_pool[GG * HD];
__device__ __align__(16) float g_cnt [GG];
__device__ int g_is64;

// index accessor valid for both int64 and int32 index buffers
__device__ __forceinline__ int IDX(const void* p, long long pos) {
    return g_is64 ? (int)((const long long*)p)[pos] : ((const int*)p)[pos];
}

// ---------------- dtype detection ------------------------------------------
// Reads only the first 8192 uint32 words (32KB) — safe under either dtype.
// int64 little-endian: odd words are high halves of values < 40000 -> all 0.
// int32: odd words are random node indices -> almost never 0.
__global__ void detect_kernel(const unsigned int* __restrict__ raw) {
    __shared__ int nz;
    if (threadIdx.x == 0) nz = 0;
    __syncthreads();
    int cnt = 0;
    for (int j = threadIdx.x; j < 4096; j += 256)
        if (raw[2 * j + 1] != 0u) cnt++;
    atomicAdd(&nz, cnt);
    __syncthreads();
    if (threadIdx.x == 0) g_is64 = (nz < 64) ? 1 : 0;
}

// ---------------- zero / degree / dinv -------------------------------------
__global__ void zero_misc_kernel() {
    int i = blockIdx.x * blockDim.x + threadIdx.x;
    if (i < NN)      g_deg[i]  = 0.f;
    if (i < GG)      g_cnt[i]  = 0.f;
    if (i < GG * HD) g_pool[i] = 0.f;
}

__global__ void zero_agg_kernel() {
    int i = blockIdx.x * blockDim.x + threadIdx.x;   // over NN*HD/4
    ((float4*)g_agg)[i] = make_float4(0.f, 0.f, 0.f, 0.f);
}

__global__ void deg_cnt_kernel(const void* __restrict__ ei,
                               const void* __restrict__ batch) {
    int i = blockIdx.x * blockDim.x + threadIdx.x;
    if (i < EE) atomicAdd(&g_deg[IDX(ei, (long long)EE + i)], 1.0f);
    if (i < NN) atomicAdd(&g_cnt[IDX(batch, i)], 1.0f);
}

__global__ void dinv_kernel() {
    int i = blockIdx.x * blockDim.x + threadIdx.x;
    if (i < NN) g_dinv[i] = rsqrtf(g_deg[i] + 1.0f);
}

// ---------------- GEMM: C[M,128] = A[M,128] @ B[128,128] -------------------
// BM=64, full N=128, full K=128 in one shot. 256 threads, 16x16 layout,
// each thread computes a 4x8 micro-tile. A tile 32KB + B 64KB dynamic smem.
__global__ __launch_bounds__(256) void gemm_kernel(const float* __restrict__ Xin,
                                                   const float* __restrict__ B,
                                                   int layer2) {
    extern __shared__ float sm[];
    float* As = sm;            // [64][128]
    float* Bs = sm + 64 * HD;  // [128][128]
    const float* A = layer2 ? (const float*)g_h : Xin;

    int tid = threadIdx.x;
    int tx = tid & 15;         // 0..15 -> 8 output cols each
    int ty = tid >> 4;         // 0..15 -> 4 output rows each

    // flat tile copies (tiles are contiguous since row width == K == 128)
    const float4* Ag4 = (const float4*)(A + (size_t)blockIdx.x * 64 * HD);
    float4* As4 = (float4*)As;
#pragma unroll
    for (int i = 0; i < 8; i++) As4[tid + i * 256] = Ag4[tid + i * 256];
    const float4* Bg4 = (const float4*)B;
    float4* Bs4 = (float4*)Bs;
#pragma unroll
    for (int i = 0; i < 16; i++) Bs4[tid + i * 256] = Bg4[tid + i * 256];
    __syncthreads();

    float acc[4][8];
#pragma unroll
    for (int i = 0; i < 4; i++)
#pragma unroll
        for (int j = 0; j < 8; j++) acc[i][j] = 0.f;

#pragma unroll 8
    for (int k = 0; k < 128; k++) {
        float a0 = As[(ty * 4 + 0) * HD + k];
        float a1 = As[(ty * 4 + 1) * HD + k];
        float a2 = As[(ty * 4 + 2) * HD + k];
        float a3 = As[(ty * 4 + 3) * HD + k];
        float4 b0 = ((float4*)(Bs + k * HD))[tx * 2 + 0];
        float4 b1 = ((float4*)(Bs + k * HD))[tx * 2 + 1];
        float bb[8] = {b0.x, b0.y, b0.z, b0.w, b1.x, b1.y, b1.z, b1.w};
        float aa[4] = {a0, a1, a2, a3};
#pragma unroll
        for (int i = 0; i < 4; i++)
#pragma unroll
            for (int j = 0; j < 8; j++) acc[i][j] += aa[i] * bb[j];
    }

#pragma unroll
    for (int i = 0; i < 4; i++) {
        size_t row = (size_t)blockIdx.x * 64 + ty * 4 + i;
        float4* crow = (float4*)(g_xw + row * HD);
        crow[tx * 2 + 0] = make_float4(acc[i][0], acc[i][1], acc[i][2], acc[i][3]);
        crow[tx * 2 + 1] = make_float4(acc[i][4], acc[i][5], acc[i][6], acc[i][7]);
    }
}

// ---------------- edge scatter: agg[dst] += xw[src] * dinv[s]*dinv[d] ------
// one warp per edge; each lane handles 4 floats (float4), vector red.
__global__ __launch_bounds__(256) void edge_kernel(const void* __restrict__ ei) {
    long long t = (long long)blockIdx.x * 256 + threadIdx.x;
    int e = (int)(t >> 5);
    if (e >= EE) return;
    int lane = threadIdx.x & 31;
    int s = IDX(ei, e);
    int d = IDX(ei, (long long)EE + e);
    float norm = __ldg(&g_dinv[s]) * __ldg(&g_dinv[d]);
    float4 v = *(const float4*)(g_xw + (size_t)s * HD + lane * 4);
    float* p = g_agg + (size_t)d * HD + lane * 4;
    asm volatile("red.global.add.v4.f32 [%0], {%1,%2,%3,%4};"
                 :: "l"(p), "f"(v.x * norm), "f"(v.y * norm),
                    "f"(v.z * norm), "f"(v.w * norm)
                 : "memory");
}

// ---------------- node epilogue: h = relu(agg + xw*dinv^2 + b) -------------
__global__ void node_kernel(const float* __restrict__ b) {
    int i = blockIdx.x * blockDim.x + threadIdx.x;   // over NN*32 float4s
    int node = i >> 5, q = i & 31;
    float di = g_dinv[node];
    float d2 = di * di;
    float4 a  = ((const float4*)g_agg)[i];
    float4 w  = ((const float4*)g_xw)[i];
    float4 bb = ((const float4*)b)[q];
    float4 h;
    h.x = fmaxf(fmaf(w.x, d2, a.x) + bb.x, 0.f);
    h.y = fmaxf(fmaf(w.y, d2, a.y) + bb.y, 0.f);
    h.z = fmaxf(fmaf(w.z, d2, a.z) + bb.z, 0.f);
    h.w = fmaxf(fmaf(w.w, d2, a.w) + bb.w, 0.f);
    ((float4*)g_h)[i] = h;
}

// ---------------- mean pool over sorted batch ------------------------------
#define POOL_BLOCKS 160
#define POOL_NODES  250          // 160 * 250 = 40000
__global__ __launch_bounds__(128) void pool_accum_kernel(const void* __restrict__ batch) {
    __shared__ float sh[GG * HD];        // 32 KB; thread t owns column t
    int t = threadIdx.x;
    for (int i = t; i < GG * HD; i += 128) sh[i] = 0.f;
    __syncthreads();
    int start = blockIdx.x * POOL_NODES;
    for (int n = start; n < start + POOL_NODES; n++) {
        int g = IDX(batch, n);
        sh[g * HD + t] += g_h[(size_t)n * HD + t];
    }
    __syncthreads();
    for (int i = t; i < GG * HD; i += 128) atomicAdd(&g_pool[i], sh[i]);
}

__global__ void pool_final_kernel(float* __restrict__ out) {
    int i = blockIdx.x * blockDim.x + threadIdx.x;
    if (i < GG * HD) out[i] = g_pool[i] / fmaxf(g_cnt[i >> 7], 1.0f);
}

// ---------------- launch ----------------------------------------------------
extern "C" void kernel_launch(void* const* d_in, const int* in_sizes, int n_in,
                              void* d_out, int out_size) {
    // Resolve inputs by element count (robust to scalar num_graphs presence):
    //   x: 5,120,000  edge_index: 1,280,000  batch: 40,000
    //   W1/W2: 16,384 (in order)   b1/b2: 128 (in order)
    const float *x = 0, *W1 = 0, *b1 = 0, *W2 = 0, *b2 = 0;
    const void  *ei = 0, *batch = 0;
    for (int i = 0; i < n_in; i++) {
        long long sz = in_sizes[i];
        if      (sz == (long long)NN * HD) x = (const float*)d_in[i];
        else if (sz == 2LL * EE)           ei = d_in[i];
        else if (sz == NN)                 batch = d_in[i];
        else if (sz == HD * HD) { if (!W1) W1 = (const float*)d_in[i];
                                  else     W2 = (const float*)d_in[i]; }
        else if (sz == HD)      { if (!b1) b1 = (const float*)d_in[i];
                                  else     b2 = (const float*)d_in[i]; }
    }
    float* out = (float*)d_out;

    cudaFuncSetAttribute((const void*)gemm_kernel,
                         cudaFuncAttributeMaxDynamicSharedMemorySize, 98304);

    const int ZB   = (NN + 255) / 256;               // 157
    const int EB   = (EE + 255) / 256;               // 2500
    const int AGGB = (NN * HD / 4) / 256;            // 5000
    const int EDGB = (EE * 32) / 256;                // 80000
    const int NODB = (NN * 32) / 256;                // 5000

    detect_kernel<<<1, 256>>>((const unsigned int*)ei);
    zero_misc_kernel<<<ZB, 256>>>();
    deg_cnt_kernel<<<EB, 256>>>(ei, batch);
    dinv_kernel<<<ZB, 256>>>();

    // layer 1
    gemm_kernel<<<625, 256, 98304>>>(x, W1, 0);
    zero_agg_kernel<<<AGGB, 256>>>();
    edge_kernel<<<EDGB, 256>>>(ei);
    node_kernel<<<NODB, 256>>>(b1);

    // layer 2
    gemm_kernel<<<625, 256, 98304>>>(x, W2, 1);
    zero_agg_kernel<<<AGGB, 256>>>();
    edge_kernel<<<EDGB, 256>>>(ei);
    node_kernel<<<NODB, 256>>>(b2);

    // pool
    pool_accum_kernel<<<POOL_BLOCKS, 128>>>(batch);
    pool_final_kernel<<<(GG * HD + 255) / 256, 256>>>(out);
}

// round 3
// speedup vs baseline: 1.3101x; 1.3101x over previous
#include <cuda_runtime.h>
#include <cuda_fp16.h>

#define NN 40000
#define EE 640000
#define HD 128
#define GG 64

// ---------------- scratch (no allocs allowed: __device__ globals) ----------
__device__ __align__(16) float  g_xw  [(size_t)NN * HD];   // x@W f32
__device__ __align__(16) __half g_xwh [(size_t)NN * HD];   // x@W fp16 (gather payload)
__device__ __align__(16) __half g_aggh[(size_t)NN * HD];   // fp16 edge accumulator
__device__ __align__(16) float  g_h   [(size_t)NN * HD];   // layer output f32
__device__ __align__(16) float  g_deg [NN];
__device__ __align__(16) float  g_dinv[NN];
__device__ __align__(16) int    g_src [EE];
__device__ __align__(16) int    g_dst [EE];
__device__ __align__(16) float  g_norm[EE];
__device__ __align__(16) float  g_pool[GG * HD];
__device__ __align__(16) float  g_cnt [GG];
__device__ int g_is64;

// index accessor valid for both int64 and int32 index buffers
__device__ __forceinline__ int IDX(const void* p, long long pos) {
    return g_is64 ? (int)((const long long*)p)[pos] : ((const int*)p)[pos];
}

// ---------------- dtype detection ------------------------------------------
// Reads first 8192 uint32 words (32KB) — safe under either dtype.
// int64 LE: odd words are high halves of values < 40000 -> all 0.
__global__ void detect_kernel(const unsigned int* __restrict__ raw) {
    __shared__ int nz;
    if (threadIdx.x == 0) nz = 0;
    __syncthreads();
    int cnt = 0;
    for (int j = threadIdx.x; j < 4096; j += 256)
        if (raw[2 * j + 1] != 0u) cnt++;
    atomicAdd(&nz, cnt);
    __syncthreads();
    if (threadIdx.x == 0) g_is64 = (nz < 64) ? 1 : 0;
}

// ---------------- prep chain ------------------------------------------------
__global__ void zero_misc_kernel() {
    int i = blockIdx.x * blockDim.x + threadIdx.x;
    if (i < NN)      g_deg[i]  = 0.f;
    if (i < GG)      g_cnt[i]  = 0.f;
    if (i < GG * HD) g_pool[i] = 0.f;
}

__global__ void convert_kernel(const void* __restrict__ ei) {
    int i = blockIdx.x * blockDim.x + threadIdx.x;
    if (i < EE) {
        g_src[i] = IDX(ei, i);
        g_dst[i] = IDX(ei, (long long)EE + i);
    }
}

__global__ void deg_cnt_kernel(const void* __restrict__ batch) {
    int i = blockIdx.x * blockDim.x + threadIdx.x;
    if (i < EE) atomicAdd(&g_deg[g_dst[i]], 1.0f);
    if (i < NN) atomicAdd(&g_cnt[IDX(batch, i)], 1.0f);
}

__global__ void dinv_kernel() {
    int i = blockIdx.x * blockDim.x + threadIdx.x;
    if (i < NN) g_dinv[i] = rsqrtf(g_deg[i] + 1.0f);
}

__global__ void norm_kernel() {
    int i = blockIdx.x * blockDim.x + threadIdx.x;
    if (i < EE) g_norm[i] = g_dinv[g_src[i]] * g_dinv[g_dst[i]];
}

// ---------------- GEMM: C[M,128] = A[M,128] @ B[128,128] -------------------
// BM=64, 256 threads, each thread a 4x8 micro-tile. Writes f32 and fp16 copies.
__global__ __launch_bounds__(256) void gemm_kernel(const float* __restrict__ Xin,
                                                   const float* __restrict__ B,
                                                   int layer2) {
    extern __shared__ float sm[];
    float* As = sm;            // [64][128]
    float* Bs = sm + 64 * HD;  // [128][128]
    const float* A = layer2 ? (const float*)g_h : Xin;

    int tid = threadIdx.x;
    int tx = tid & 15;         // 8 output cols each
    int ty = tid >> 4;         // 4 output rows each

    const float4* Ag4 = (const float4*)(A + (size_t)blockIdx.x * 64 * HD);
    float4* As4 = (float4*)As;
#pragma unroll
    for (int i = 0; i < 8; i++) As4[tid + i * 256] = Ag4[tid + i * 256];
    const float4* Bg4 = (const float4*)B;
    float4* Bs4 = (float4*)Bs;
#pragma unroll
    for (int i = 0; i < 16; i++) Bs4[tid + i * 256] = Bg4[tid + i * 256];
    __syncthreads();

    float acc[4][8];
#pragma unroll
    for (int i = 0; i < 4; i++)
#pragma unroll
        for (int j = 0; j < 8; j++) acc[i][j] = 0.f;

#pragma unroll 8
    for (int k = 0; k < 128; k++) {
        float aa[4];
#pragma unroll
        for (int i = 0; i < 4; i++) aa[i] = As[(ty * 4 + i) * HD + k];
        float4 b0 = ((float4*)(Bs + k * HD))[tx * 2 + 0];
        float4 b1 = ((float4*)(Bs + k * HD))[tx * 2 + 1];
        float bb[8] = {b0.x, b0.y, b0.z, b0.w, b1.x, b1.y, b1.z, b1.w};
#pragma unroll
        for (int i = 0; i < 4; i++)
#pragma unroll
            for (int j = 0; j < 8; j++) acc[i][j] += aa[i] * bb[j];
    }

#pragma unroll
    for (int i = 0; i < 4; i++) {
        size_t row = (size_t)blockIdx.x * 64 + ty * 4 + i;
        float4* crow = (float4*)(g_xw + row * HD);
        crow[tx * 2 + 0] = make_float4(acc[i][0], acc[i][1], acc[i][2], acc[i][3]);
        crow[tx * 2 + 1] = make_float4(acc[i][4], acc[i][5], acc[i][6], acc[i][7]);
        // fp16 copy for the edge gather
        __half2 hp[4];
#pragma unroll
        for (int j = 0; j < 4; j++)
            hp[j] = __floats2half2_rn(acc[i][2 * j], acc[i][2 * j + 1]);
        ((uint4*)(g_xwh + row * HD))[tx * 2 / 2] = *(uint4*)hp;  // 8 halves = 16B
    }
}

// ---------------- edge scatter: aggh[dst] += xwh[src] * norm (fp16) --------
// 16 lanes per edge, each lane one uint4 (8 halves); vector fp16x2 red.
__global__ __launch_bounds__(256) void edge_kernel() {
    long long t = (long long)blockIdx.x * 256 + threadIdx.x;
    int e = (int)(t >> 4);
    if (e >= EE) return;
    int sub = threadIdx.x & 15;
    int s = g_src[e];
    int d = g_dst[e];
    float nm = g_norm[e];
    uint4 v = ((const uint4*)g_xwh)[(size_t)s * 16 + sub];
    __half2* hv = (__half2*)&v;
#pragma unroll
    for (int i = 0; i < 4; i++) {
        float2 f = __half22float2(hv[i]);
        hv[i] = __floats2half2_rn(f.x * nm, f.y * nm);
    }
    __half* p = g_aggh + (size_t)d * HD + sub * 8;
    asm volatile("red.global.add.noftz.v4.f16x2 [%0], {%1,%2,%3,%4};"
                 :: "l"(p), "r"(v.x), "r"(v.y), "r"(v.z), "r"(v.w)
                 : "memory");
}

// ---------------- node epilogue: h = relu(aggh + xw*dinv^2 + b) ------------
__global__ void node_kernel(const float* __restrict__ b) {
    int i = blockIdx.x * blockDim.x + threadIdx.x;   // over NN*32 float4s
    int node = i >> 5, q = i & 31;
    float di = g_dinv[node];
    float d2 = di * di;
    uint2 av = ((const uint2*)g_aggh)[i];
    float2 a0 = __half22float2(*(__half2*)&av.x);
    float2 a1 = __half22float2(*(__half2*)&av.y);
    float4 w  = ((const float4*)g_xw)[i];
    float4 bb = ((const float4*)b)[q];
    float4 h;
    h.x = fmaxf(fmaf(w.x, d2, a0.x) + bb.x, 0.f);
    h.y = fmaxf(fmaf(w.y, d2, a0.y) + bb.y, 0.f);
    h.z = fmaxf(fmaf(w.z, d2, a1.x) + bb.z, 0.f);
    h.w = fmaxf(fmaf(w.w, d2, a1.y) + bb.w, 0.f);
    ((float4*)g_h)[i] = h;
}

// ---------------- mean pool over sorted batch ------------------------------
#define POOL_BLOCKS 160
#define POOL_NODES  250          // 160 * 250 = 40000
__global__ __launch_bounds__(128) void pool_accum_kernel(const void* __restrict__ batch) {
    __shared__ float sh[GG * HD];        // 32 KB; thread t owns column t
    int t = threadIdx.x;
    for (int i = t; i < GG * HD; i += 128) sh[i] = 0.f;
    __syncthreads();
    int start = blockIdx.x * POOL_NODES;
    for (int n = start; n < start + POOL_NODES; n++) {
        int g = IDX(batch, n);
        sh[g * HD + t] += g_h[(size_t)n * HD + t];
    }
    __syncthreads();
    for (int i = t; i < GG * HD; i += 128) atomicAdd(&g_pool[i], sh[i]);
}

__global__ void pool_final_kernel(float* __restrict__ out) {
    int i = blockIdx.x * blockDim.x + threadIdx.x;
    if (i < GG * HD) out[i] = g_pool[i] / fmaxf(g_cnt[i >> 7], 1.0f);
}

// ---------------- launch ----------------------------------------------------
extern "C" void kernel_launch(void* const* d_in, const int* in_sizes, int n_in,
                              void* d_out, int out_size) {
    // Resolve inputs by element count (robust to scalar num_graphs presence)
    const float *x = 0, *W1 = 0, *b1 = 0, *W2 = 0, *b2 = 0;
    const void  *ei = 0, *batch = 0;
    for (int i = 0; i < n_in; i++) {
        long long sz = in_sizes[i];
        if      (sz == (long long)NN * HD) x = (const float*)d_in[i];
        else if (sz == 2LL * EE)           ei = d_in[i];
        else if (sz == NN)                 batch = d_in[i];
        else if (sz == HD * HD) { if (!W1) W1 = (const float*)d_in[i];
                                  else     W2 = (const float*)d_in[i]; }
        else if (sz == HD)      { if (!b1) b1 = (const float*)d_in[i];
                                  else     b2 = (const float*)d_in[i]; }
    }
    float* out = (float*)d_out;

    // one-time host-side resources (no device allocs)
    static cudaStream_t sA = 0;
    static cudaEvent_t ev0 = 0, ev1 = 0, ev2 = 0, ev3 = 0;
    static void* aggh_addr = 0;
    if (!sA) {
        cudaStreamCreateWithFlags(&sA, cudaStreamNonBlocking);
        cudaEventCreateWithFlags(&ev0, cudaEventDisableTiming);
        cudaEventCreateWithFlags(&ev1, cudaEventDisableTiming);
        cudaEventCreateWithFlags(&ev2, cudaEventDisableTiming);
        cudaEventCreateWithFlags(&ev3, cudaEventDisableTiming);
        cudaGetSymbolAddress(&aggh_addr, g_aggh);
        cudaFuncSetAttribute((const void*)gemm_kernel,
                             cudaFuncAttributeMaxDynamicSharedMemorySize, 98304);
    }

    const int ZB   = (NN + 255) / 256;       // 157
    const int EB   = (EE + 255) / 256;       // 2500
    const int EDGB = (EE * 16) / 256;        // 40000
    const int NODB = (NN * 32) / 256;        // 5000
    const size_t AGGB_BYTES = (size_t)NN * HD * sizeof(__half);

    // fork: GEMM1 on sA, prep chain on main stream
    cudaEventRecord(ev0, 0);
    cudaStreamWaitEvent(sA, ev0, 0);
    gemm_kernel<<<625, 256, 98304, sA>>>(x, W1, 0);
    cudaEventRecord(ev1, sA);

    detect_kernel<<<1, 256>>>((const unsigned int*)ei);
    zero_misc_kernel<<<ZB, 256>>>();
    convert_kernel<<<EB, 256>>>(ei);
    deg_cnt_kernel<<<EB, 256>>>(batch);
    dinv_kernel<<<ZB, 256>>>();
    norm_kernel<<<EB, 256>>>();
    cudaMemsetAsync(aggh_addr, 0, AGGB_BYTES, 0);

    // join: layer-1 edge phase
    cudaStreamWaitEvent(0, ev1, 0);
    edge_kernel<<<EDGB, 256>>>();
    node_kernel<<<NODB, 256>>>(b1);
    cudaEventRecord(ev2, 0);

    // fork: GEMM2 on sA while main stream re-zeros the fp16 accumulator
    cudaStreamWaitEvent(sA, ev2, 0);
    gemm_kernel<<<625, 256, 98304, sA>>>(x, W2, 1);
    cudaEventRecord(ev3, sA);
    cudaMemsetAsync(aggh_addr, 0, AGGB_BYTES, 0);

    // join: layer-2 edge phase
    cudaStreamWaitEvent(0, ev3, 0);
    edge_kernel<<<EDGB, 256>>>();
    node_kernel<<<NODB, 256>>>(b2);

    // pool
    pool_accum_kernel<<<POOL_BLOCKS, 128>>>(batch);
    pool_final_kernel<<<(GG * HD + 255) / 256, 256>>>(out);
}

// round 4
// speedup vs baseline: 2.0755x; 1.5842x over previous
#include <cuda_runtime.h>
#include <cuda_fp16.h>

#define NN 40000
#define EE 640000
#define HD 128
#define GG 64
#define PADH 136   // padded halves per smem row (272B: conflict-free ldmatrix)

// ---------------- scratch (no allocs: __device__ globals) -------------------
__device__ __align__(16) float  g_xw  [(size_t)NN * HD];   // x@W f32
__device__ __align__(16) __half g_xwh [(size_t)NN * HD];   // x@W fp16 (gather)
__device__ __align__(16) __half g_aggh[(size_t)NN * HD];   // fp16 edge accum
__device__ __align__(16) float  g_h   [(size_t)NN * HD];   // layer output f32
__device__ __align__(16) float  g_deg [NN];
__device__ __align__(16) float  g_dinv[NN];
__device__ __align__(16) int    g_src [EE];
__device__ __align__(16) int    g_dst [EE];
__device__ __align__(16) float  g_pool[GG * HD];
__device__ __align__(16) float  g_cnt [GG];
__device__ int g_is64;

__device__ __forceinline__ int IDX(const void* p, long long pos) {
    return g_is64 ? (int)((const long long*)p)[pos] : ((const int*)p)[pos];
}

// ---------------- dtype detection (reads first 32KB only) -------------------
__global__ void detect_kernel(const unsigned int* __restrict__ raw) {
    __shared__ int nz;
    if (threadIdx.x == 0) nz = 0;
    __syncthreads();
    int cnt = 0;
    for (int j = threadIdx.x; j < 4096; j += 256)
        if (raw[2 * j + 1] != 0u) cnt++;
    atomicAdd(&nz, cnt);
    __syncthreads();
    if (threadIdx.x == 0) g_is64 = (nz < 64) ? 1 : 0;
}

// ---------------- prep ------------------------------------------------------
__global__ void zero_misc_kernel() {
    int i = blockIdx.x * blockDim.x + threadIdx.x;
    if (i < NN)      g_deg[i]  = 0.f;
    if (i < GG)      g_cnt[i]  = 0.f;
    if (i < GG * HD) g_pool[i] = 0.f;
}

// fused: index convert + degree + per-graph counts
__global__ void conv_deg_kernel(const void* __restrict__ ei,
                                const void* __restrict__ batch) {
    int i = blockIdx.x * blockDim.x + threadIdx.x;
    if (i < EE) {
        int s = IDX(ei, i);
        int d = IDX(ei, (long long)EE + i);
        g_src[i] = s;
        g_dst[i] = d;
        atomicAdd(&g_deg[d], 1.0f);
    }
    if (i < NN) atomicAdd(&g_cnt[IDX(batch, i)], 1.0f);
}

__global__ void dinv_kernel() {
    int i = blockIdx.x * blockDim.x + threadIdx.x;
    if (i < NN) g_dinv[i] = rsqrtf(g_deg[i] + 1.0f);
}

// ---------------- tensor-core GEMM: C[M,128] = A[M,128] @ W[128,128] --------
// fp16 inputs (converted in-kernel from f32), f32 accumulate via mma.sync.
// Block tile 128x128, full K=128 in smem, 8 warps in 4(m) x 2(n) layout.
__global__ __launch_bounds__(256) void gemm_tc_kernel(const float* __restrict__ A,
                                                      const float* __restrict__ W) {
    extern __shared__ __half smh[];
    __half* As = smh;                 // [128][PADH]
    __half* Bs = smh + 128 * PADH;    // [128][PADH]  (Bs[k][n])

    int tid = threadIdx.x;
    long long mbase = (long long)blockIdx.x * 128;

    // fill A tile (f32 -> fp16), guarded on row < NN
#pragma unroll
    for (int i = 0; i < 16; i++) {
        int idx = i * 256 + tid;          // 0..4095
        int row = idx >> 5, c4 = idx & 31;
        long long grow = mbase + row;
        float4 v = (grow < NN) ? ((const float4*)A)[grow * 32 + c4]
                               : make_float4(0.f, 0.f, 0.f, 0.f);
        __half2* dst = (__half2*)(As + row * PADH + c4 * 4);
        dst[0] = __floats2half2_rn(v.x, v.y);
        dst[1] = __floats2half2_rn(v.z, v.w);
    }
    // fill B tile (W is [k][n] row-major already)
#pragma unroll
    for (int i = 0; i < 16; i++) {
        int idx = i * 256 + tid;
        int row = idx >> 5, c4 = idx & 31;
        float4 v = ((const float4*)W)[row * 32 + c4];
        __half2* dst = (__half2*)(Bs + row * PADH + c4 * 4);
        dst[0] = __floats2half2_rn(v.x, v.y);
        dst[1] = __floats2half2_rn(v.z, v.w);
    }
    __syncthreads();

    int wid = tid >> 5, lane = tid & 31;
    int wm = (wid & 3) * 32;      // 32 rows per warp
    int wn = (wid >> 2) * 64;     // 64 cols per warp

    float acc[2][8][4];
#pragma unroll
    for (int mt = 0; mt < 2; mt++)
#pragma unroll
        for (int nt = 0; nt < 8; nt++)
#pragma unroll
            for (int q = 0; q < 4; q++) acc[mt][nt][q] = 0.f;

#pragma unroll
    for (int kk = 0; kk < 8; kk++) {
        // A fragments: two m16 tiles
        unsigned a[2][4];
#pragma unroll
        for (int mt = 0; mt < 2; mt++) {
            int r = lane & 15, c = (lane >> 4) * 8;
            unsigned addr = (unsigned)__cvta_generic_to_shared(
                As + (wm + mt * 16 + r) * PADH + kk * 16 + c);
            asm volatile("ldmatrix.sync.aligned.m8n8.x4.shared.b16 {%0,%1,%2,%3}, [%4];"
                         : "=r"(a[mt][0]), "=r"(a[mt][1]), "=r"(a[mt][2]), "=r"(a[mt][3])
                         : "r"(addr));
        }
        // B fragments: eight n8 tiles via 4x ldmatrix.x4.trans
        unsigned b[8][2];
#pragma unroll
        for (int nt2 = 0; nt2 < 4; nt2++) {
            int krow = kk * 16 + ((lane >> 3) & 1) * 8 + (lane & 7);
            int ncol = wn + nt2 * 16 + (lane >> 4) * 8;
            unsigned addr = (unsigned)__cvta_generic_to_shared(Bs + krow * PADH + ncol);
            asm volatile("ldmatrix.sync.aligned.m8n8.x4.trans.shared.b16 {%0,%1,%2,%3}, [%4];"
                         : "=r"(b[nt2 * 2][0]), "=r"(b[nt2 * 2][1]),
                           "=r"(b[nt2 * 2 + 1][0]), "=r"(b[nt2 * 2 + 1][1])
                         : "r"(addr));
        }
#pragma unroll
        for (int mt = 0; mt < 2; mt++)
#pragma unroll
            for (int nt = 0; nt < 8; nt++)
                asm volatile("mma.sync.aligned.m16n8k16.row.col.f32.f16.f16.f32 "
                             "{%0,%1,%2,%3}, {%4,%5,%6,%7}, {%8,%9}, {%0,%1,%2,%3};"
                             : "+f"(acc[mt][nt][0]), "+f"(acc[mt][nt][1]),
                               "+f"(acc[mt][nt][2]), "+f"(acc[mt][nt][3])
                             : "r"(a[mt][0]), "r"(a[mt][1]), "r"(a[mt][2]), "r"(a[mt][3]),
                               "r"(b[nt][0]), "r"(b[nt][1]));
    }

    // epilogue: write f32 (g_xw) and fp16 (g_xwh)
    int r0 = lane >> 2, cq = (lane & 3) * 2;
#pragma unroll
    for (int mt = 0; mt < 2; mt++) {
        long long rowA = mbase + wm + mt * 16 + r0;
        long long rowB = rowA + 8;
#pragma unroll
        for (int nt = 0; nt < 8; nt++) {
            int col = wn + nt * 8 + cq;
            if (rowA < NN) {
                *(float2*)&g_xw[rowA * HD + col] = make_float2(acc[mt][nt][0], acc[mt][nt][1]);
                *(__half2*)&g_xwh[rowA * HD + col] = __floats2half2_rn(acc[mt][nt][0], acc[mt][nt][1]);
            }
            if (rowB < NN) {
                *(float2*)&g_xw[rowB * HD + col] = make_float2(acc[mt][nt][2], acc[mt][nt][3]);
                *(__half2*)&g_xwh[rowB * HD + col] = __floats2half2_rn(acc[mt][nt][2], acc[mt][nt][3]);
            }
        }
    }
}

// ---------------- edge scatter: aggh[dst] += xwh[src] * dinv[s]*dinv[d] -----
__global__ __launch_bounds__(256) void edge_kernel() {
    long long t = (long long)blockIdx.x * 256 + threadIdx.x;
    int e = (int)(t >> 4);
    if (e >= EE) return;
    int sub = threadIdx.x & 15;
    int s = g_src[e];
    int d = g_dst[e];
    float nm = __ldg(&g_dinv[s]) * __ldg(&g_dinv[d]);
    uint4 v = ((const uint4*)g_xwh)[(size_t)s * 16 + sub];
    __half2* hv = (__half2*)&v;
#pragma unroll
    for (int i = 0; i < 4; i++) {
        float2 f = __half22float2(hv[i]);
        hv[i] = __floats2half2_rn(f.x * nm, f.y * nm);
    }
    __half* p = g_aggh + (size_t)d * HD + sub * 8;
    asm volatile("red.global.add.noftz.v4.f16x2 [%0], {%1,%2,%3,%4};"
                 :: "l"(p), "r"(v.x), "r"(v.y), "r"(v.z), "r"(v.w)
                 : "memory");
}

// ---------------- node epilogue: h = relu(aggh + xw*dinv^2 + b) -------------
__global__ void node_kernel(const float* __restrict__ b) {
    int i = blockIdx.x * blockDim.x + threadIdx.x;   // over NN*32 float4s
    int node = i >> 5, q = i & 31;
    float di = g_dinv[node];
    float d2 = di * di;
    uint2 av = ((const uint2*)g_aggh)[i];
    float2 a0 = __half22float2(*(__half2*)&av.x);
    float2 a1 = __half22float2(*(__half2*)&av.y);
    float4 w  = ((const float4*)g_xw)[i];
    float4 bb = ((const float4*)b)[q];
    float4 h;
    h.x = fmaxf(fmaf(w.x, d2, a0.x) + bb.x, 0.f);
    h.y = fmaxf(fmaf(w.y, d2, a0.y) + bb.y, 0.f);
    h.z = fmaxf(fmaf(w.z, d2, a1.x) + bb.z, 0.f);
    h.w = fmaxf(fmaf(w.w, d2, a1.y) + bb.w, 0.f);
    ((float4*)g_h)[i] = h;
}

// ---------------- mean pool over sorted batch -------------------------------
#define POOL_BLOCKS 320
#define POOL_NODES  125          // 320 * 125 = 40000
__global__ __launch_bounds__(128) void pool_accum_kernel(const void* __restrict__ batch) {
    __shared__ float sh[GG * HD];        // 32 KB; thread t owns column t
    int t = threadIdx.x;
    for (int i = t; i < GG * HD; i += 128) sh[i] = 0.f;
    __syncthreads();
    int start = blockIdx.x * POOL_NODES;
    for (int n = start; n < start + POOL_NODES; n++) {
        int g = IDX(batch, n);
        sh[g * HD + t] += g_h[(size_t)n * HD + t];
    }
    __syncthreads();
    for (int i = t; i < GG * HD; i += 128) atomicAdd(&g_pool[i], sh[i]);
}

__global__ void pool_final_kernel(float* __restrict__ out) {
    int i = blockIdx.x * blockDim.x + threadIdx.x;
    if (i < GG * HD) out[i] = g_pool[i] / fmaxf(g_cnt[i >> 7], 1.0f);
}

// ---------------- launch -----------------------------------------------------
extern "C" void kernel_launch(void* const* d_in, const int* in_sizes, int n_in,
                              void* d_out, int out_size) {
    const float *x = 0, *W1 = 0, *b1 = 0, *W2 = 0, *b2 = 0;
    const void  *ei = 0, *batch = 0;
    for (int i = 0; i < n_in; i++) {
        long long sz = in_sizes[i];
        if      (sz == (long long)NN * HD) x = (const float*)d_in[i];
        else if (sz == 2LL * EE)           ei = d_in[i];
        else if (sz == NN)                 batch = d_in[i];
        else if (sz == HD * HD) { if (!W1) W1 = (const float*)d_in[i];
                                  else     W2 = (const float*)d_in[i]; }
        else if (sz == HD)      { if (!b1) b1 = (const float*)d_in[i];
                                  else     b2 = (const float*)d_in[i]; }
    }
    float* out = (float*)d_out;

    static cudaStream_t sA = 0;
    static cudaEvent_t ev0 = 0, ev1 = 0, ev2 = 0, ev3 = 0;
    static void* aggh_addr = 0;
    static void* h_addr = 0;
    if (!sA) {
        cudaStreamCreateWithFlags(&sA, cudaStreamNonBlocking);
        cudaEventCreateWithFlags(&ev0, cudaEventDisableTiming);
        cudaEventCreateWithFlags(&ev1, cudaEventDisableTiming);
        cudaEventCreateWithFlags(&ev2, cudaEventDisableTiming);
        cudaEventCreateWithFlags(&ev3, cudaEventDisableTiming);
        cudaGetSymbolAddress(&aggh_addr, g_aggh);
        cudaGetSymbolAddress(&h_addr, g_h);
        cudaFuncSetAttribute((const void*)gemm_tc_kernel,
                             cudaFuncAttributeMaxDynamicSharedMemorySize,
                             2 * 128 * PADH * (int)sizeof(__half));
    }

    const int ZB   = (NN + 255) / 256;       // 157
    const int EB   = (EE + 255) / 256;       // 2500
    const int EDGB = (EE * 16) / 256;        // 40000
    const int NODB = (NN * 32) / 256;        // 5000
    const int GEMMB = (NN + 127) / 128;      // 313
    const int GSM  = 2 * 128 * PADH * (int)sizeof(__half);  // 69632
    const size_t AGG_BYTES = (size_t)NN * HD * sizeof(__half);

    // fork: GEMM1 + aggh memset on sA; prep chain on main stream
    cudaEventRecord(ev0, 0);
    cudaStreamWaitEvent(sA, ev0, 0);
    cudaMemsetAsync(aggh_addr, 0, AGG_BYTES, sA);
    gemm_tc_kernel<<<GEMMB, 256, GSM, sA>>>(x, W1);
    cudaEventRecord(ev1, sA);

    detect_kernel<<<1, 256>>>((const unsigned int*)ei);
    zero_misc_kernel<<<ZB, 256>>>();
    conv_deg_kernel<<<EB, 256>>>(ei, batch);
    dinv_kernel<<<ZB, 256>>>();

    // join: layer-1 edge phase
    cudaStreamWaitEvent(0, ev1, 0);
    edge_kernel<<<EDGB, 256>>>();
    node_kernel<<<NODB, 256>>>(b1);
    cudaEventRecord(ev2, 0);

    // fork: re-zero accumulator on sA while main stream runs GEMM2
    cudaStreamWaitEvent(sA, ev2, 0);
    cudaMemsetAsync(aggh_addr, 0, AGG_BYTES, sA);
    cudaEventRecord(ev3, sA);
    gemm_tc_kernel<<<GEMMB, 256, GSM>>>((const float*)h_addr, W2);

    // join: layer-2 edge phase
    cudaStreamWaitEvent(0, ev3, 0);
    edge_kernel<<<EDGB, 256>>>();
    node_kernel<<<NODB, 256>>>(b2);

    // pool
    pool_accum_kernel<<<POOL_BLOCKS, 128>>>(batch);
    pool_final_kernel<<<(GG * HD + 255) / 256, 256>>>(out);
}